// round 14
// baseline (speedup 1.0000x reference)
#include <cuda_runtime.h>
#include <cuda_bf16.h>
#include <cuda_fp16.h>
#include <cstdint>
#include <cstddef>

// ---------------- Problem constants ----------------
#define PP 20000   // total proxies
#define CC 1000    // num classes
#define DD 512     // embedding dim
#define BB 4096    // eval batch
#define PPAD 20224 // 158*128 padded proxies
#define NTILES 158 // p tiles of 128
#define MTILES 32  // b tiles of 128
#define NSTAGES 24 // virtual K = [h*m(512) | m*h(512) | h*h(512)], 64 fp16 per stage
#define SCALE_STAGE 15  // after this stage: acc *= 2^-11 (cross terms done)
#define STAGEB 32768    // per-buffer smem: A 16KB + B 16KB
#define NBUF 3
#define GSMEM (NBUF * STAGEB)   // 96KB -> 2 CTAs per SM

// ---------------- Device scratch (no allocs allowed) ----------------
__device__ float  g_xT[(size_t)BB * PP];         // 327 MB  x transposed [b][p]
__device__ float  g_outT[(size_t)BB * CC];       // 16 MB   out transposed [b][c]
__device__ int    g_cstart[CC + 1];              // CSR class offsets (ids sorted)
__device__ __half g_Ah[2 * (size_t)BB * DD];     // data fp16 terms: h, m*2^11
__device__ __half g_Bh[2 * (size_t)PPAD * DD];   // w1 fp16 terms: h, m*2^11 (pad 0)

#define ASZH ((size_t)BB * DD * 2)               // bytes per A term
#define BSZH ((size_t)PPAD * DD * 2)             // bytes per B term

// ---------------- small helpers ----------------
__device__ __forceinline__ uint32_t smem_u32(const void* p) {
    uint32_t a;
    asm("{ .reg .u64 t; cvta.to.shared.u64 t, %1; cvt.u32.u64 %0, t; }"
        : "=r"(a) : "l"(p));
    return a;
}
#define CP_ASYNC16(dst, src) \
    asm volatile("cp.async.cg.shared.global [%0], [%1], 16;" :: "r"(dst), "l"(src))
#define CP_COMMIT asm volatile("cp.async.commit_group;" ::: "memory")
#define CP_WAIT1  asm volatile("cp.async.wait_group 1;" ::: "memory")
#define CP_WAIT0  asm volatile("cp.async.wait_group 0;" ::: "memory")

#define MMA_F16(c, a0, a1, a2, a3, b0, b1) \
    asm volatile( \
        "mma.sync.aligned.m16n8k16.row.col.f32.f16.f16.f32 " \
        "{%0,%1,%2,%3}, {%4,%5,%6,%7}, {%8,%9}, {%0,%1,%2,%3};" \
        : "+f"((c)[0]), "+f"((c)[1]), "+f"((c)[2]), "+f"((c)[3]) \
        : "r"(a0), "r"(a1), "r"(a2), "r"(a3), "r"(b0), "r"(b1))

#define LDSM_X4(r0, r1, r2, r3, addr) \
    asm volatile("ldmatrix.sync.aligned.m8n8.x4.shared.b16 {%0,%1,%2,%3}, [%4];" \
        : "=r"(r0), "=r"(r1), "=r"(r2), "=r"(r3) : "r"(addr))

// Order-preserving float<->uint key (for atomic min on floats)
__device__ __forceinline__ unsigned int f2key(float f) {
    unsigned int u = __float_as_uint(f);
    return (u & 0x80000000u) ? ~u : (u | 0x80000000u);
}
__device__ __forceinline__ float key2f(unsigned int k) {
    unsigned int u = (k & 0x80000000u) ? (k & 0x7FFFFFFFu) : ~k;
    return __uint_as_float(u);
}

// ---------------- 1) L2-normalize + scaled 2-term fp16 split (fused A+B) -----
// h = fp16(x); m~ = fp16((x - h) * 2^11). blocks [0,BB) -> data, rest -> w1.
__global__ void norm_split_kernel(const float* __restrict__ data,
                                  const float* __restrict__ w1) {
    int blk = blockIdx.x;
    int tid = threadIdx.x;  // 128
    const float* in;
    __half *hp, *mp;
    bool valid;
    if (blk < BB) {
        in = data + ((size_t)blk << 9);
        hp = g_Ah + ((size_t)blk << 9);
        mp = hp + (size_t)BB * DD;
        valid = true;
    } else {
        int row = blk - BB;
        in = w1 + ((size_t)row << 9);
        hp = g_Bh + ((size_t)row << 9);
        mp = hp + (size_t)PPAD * DD;
        valid = (row < PP);
    }
    if (!valid) {  // zero-pad rows -> MMA contributes 0
        uint2 z = make_uint2(0u, 0u);
        reinterpret_cast<uint2*>(hp)[tid] = z;
        reinterpret_cast<uint2*>(mp)[tid] = z;
        return;
    }
    float4 v = reinterpret_cast<const float4*>(in)[tid];
    float ss = v.x * v.x + v.y * v.y + v.z * v.z + v.w * v.w;
#pragma unroll
    for (int o = 16; o > 0; o >>= 1) ss += __shfl_xor_sync(0xffffffffu, ss, o);
    __shared__ float ws[4];
    if ((tid & 31) == 0) ws[tid >> 5] = ss;
    __syncthreads();
    float nrm = fmaxf(sqrtf(ws[0] + ws[1] + ws[2] + ws[3]), 1e-12f);
    float x[4] = {v.x / nrm, v.y / nrm, v.z / nrm, v.w / nrm};
    __half hh[4], mm[4];
#pragma unroll
    for (int j = 0; j < 4; ++j) {
        __half h = __float2half_rn(x[j]);
        float r = x[j] - __half2float(h);
        hh[j] = h;
        mm[j] = __float2half_rn(r * 2048.0f);
    }
    __half2* h2 = reinterpret_cast<__half2*>(hp);
    __half2* m2 = reinterpret_cast<__half2*>(mp);
    __half2 t;
    t.x = hh[0]; t.y = hh[1]; h2[2 * tid] = t;
    t.x = hh[2]; t.y = hh[3]; h2[2 * tid + 1] = t;
    t.x = mm[0]; t.y = mm[1]; m2[2 * tid] = t;
    t.x = mm[2]; t.y = mm[3]; m2[2 * tid + 1] = t;
}

// ---------------- fused segment-id decode + CSR offsets ----------------
__global__ void seg_csr_kernel(const void* __restrict__ s) {
    const int* w = (const int*)s;
    bool is64 = (w[19999] == 0);
    int i = blockIdx.x * 256 + threadIdx.x;
    if (i < PP) {
        int v = is64 ? (int)((const long long*)s)[i] : w[i];
        v = min(max(v, 0), CC - 1);
        int prev = -1;
        if (i > 0) {
            int pv = is64 ? (int)((const long long*)s)[i - 1] : w[i - 1];
            prev = min(max(pv, 0), CC - 1);
        }
        for (int c = prev + 1; c <= v; ++c) g_cstart[c] = i;
        if (i == PP - 1)
            for (int c = v + 1; c <= CC; ++c) g_cstart[c] = PP;
    }
}

// ---------------- 2) scaled-fp16 split GEMM, 2 CTAs/SM (unchanged R12) -------
__global__ void __launch_bounds__(256, 2) tc_gemm_kernel() {
    extern __shared__ char smem[];
    const int tid = threadIdx.x;
    const int wid = tid >> 5, lane = tid & 31;
    const int wm = wid & 1, wn = wid >> 1;
    const int g = lane >> 2, tig = lane & 3;
    const int t7 = lane & 7, t15 = lane & 15;
    const int m0 = blockIdx.x * 128;
    const int n0 = blockIdx.y * 128;
    const uint32_t sbase = smem_u32(smem);

    const uint32_t a_row_off = (uint32_t)((wm * 64 + t15) << 7);
    const int a_kq_add = lane >> 4;
    const uint32_t b_row_off = (uint32_t)((wn * 32 + t7 + ((lane & 16) >> 1)) << 7);
    const int b_kq_add = (lane >> 3) & 1;

    float acc[4][4][4];
#pragma unroll
    for (int a = 0; a < 4; ++a)
#pragma unroll
        for (int b = 0; b < 4; ++b)
#pragma unroll
            for (int c = 0; c < 4; ++c) acc[a][b][c] = 0.f;

    auto load_stage = [&](int ks, int buf) {
        int grp = ks >> 3;                               // 0: h*m, 1: m*h, 2: h*h
        const char* abase = (const char*)g_Ah + ((grp == 1) ? ASZH : 0);
        const char* bbase = (const char*)g_Bh + ((grp == 0) ? BSZH : 0);
        int kbyte = (ks & 7) << 7;                       // 128B per 64 fp16
        uint32_t sbuf = sbase + buf * STAGEB;
#pragma unroll
        for (int i = 0; i < 8; ++i) {
            int idx = tid + (i << 8);
            if (idx < 1024) {                            // A: 128 rows x 8 quads
                int r = idx >> 3, q = idx & 7;
                const char* src = abase + (size_t)(m0 + r) * 1024 + kbyte + (q << 4);
                uint32_t dst = sbuf + (r << 7) + ((q ^ (r & 7)) << 4);
                CP_ASYNC16(dst, src);
            } else {                                     // B: 128 rows x 8 quads
                int j = idx - 1024;
                int r = j >> 3, q = j & 7;
                const char* src = bbase + (size_t)(n0 + r) * 1024 + kbyte + (q << 4);
                uint32_t dst = sbuf + 16384 + (r << 7) + ((q ^ (r & 7)) << 4);
                CP_ASYNC16(dst, src);
            }
        }
    };

    load_stage(0, 0); CP_COMMIT;
    load_stage(1, 1); CP_COMMIT;

#pragma unroll 1
    for (int ks = 0; ks < NSTAGES; ++ks) {
        if (ks + 1 < NSTAGES) { CP_WAIT1; } else { CP_WAIT0; }
        __syncthreads();     // stage ks resident; buffer (ks+2)%NBUF free
        if (ks + 2 < NSTAGES) { load_stage(ks + 2, (ks + 2) % NBUF); CP_COMMIT; }

        uint32_t sA = sbase + (ks % NBUF) * STAGEB;
        uint32_t sB = sA + 16384;
#pragma unroll
        for (int s = 0; s < 4; ++s) {                    // 4 x k16 per stage
            uint32_t a[4][4];
            {
                uint32_t qa = (uint32_t)(((2 * s + a_kq_add) ^ t7) << 4);
#pragma unroll
                for (int mt = 0; mt < 4; ++mt) {
                    uint32_t addr = sA + a_row_off + (uint32_t)(mt << 11) + qa;
                    LDSM_X4(a[mt][0], a[mt][1], a[mt][2], a[mt][3], addr);
                }
            }
            uint32_t bf[2][4];
            {
                uint32_t qb = (uint32_t)(((2 * s + b_kq_add) ^ t7) << 4);
#pragma unroll
                for (int ntp = 0; ntp < 2; ++ntp) {
                    uint32_t addr = sB + b_row_off + (uint32_t)(ntp << 11) + qb;
                    LDSM_X4(bf[ntp][0], bf[ntp][1], bf[ntp][2], bf[ntp][3], addr);
                }
            }
#pragma unroll
            for (int nt = 0; nt < 4; ++nt) {
                uint32_t b0 = bf[nt >> 1][(nt & 1) * 2];
                uint32_t b1 = bf[nt >> 1][(nt & 1) * 2 + 1];
#pragma unroll
                for (int mt = 0; mt < 4; ++mt)
                    MMA_F16(acc[mt][nt], a[mt][0], a[mt][1], a[mt][2], a[mt][3], b0, b1);
            }
        }

        if (ks == SCALE_STAGE) {  // cross terms accumulated: undo the 2^11 scale
#pragma unroll
            for (int mt = 0; mt < 4; ++mt)
#pragma unroll
                for (int nt = 0; nt < 4; ++nt)
#pragma unroll
                    for (int c = 0; c < 4; ++c)
                        acc[mt][nt][c] *= 4.8828125e-4f;   // exact 2^-11
        }
    }

    // epilogue: direct fp32 stores (32B-coalesced per quad)
#pragma unroll
    for (int mt = 0; mt < 4; ++mt) {
        int row0 = m0 + wm * 64 + mt * 16 + g;
#pragma unroll
        for (int nt = 0; nt < 4; ++nt) {
            int p = n0 + wn * 32 + nt * 8 + tig * 2;
            if (p < PP) {
                *reinterpret_cast<float2*>(g_xT + (size_t)row0 * PP + p) =
                    make_float2(acc[mt][nt][0], acc[mt][nt][1]);
                *reinterpret_cast<float2*>(g_xT + (size_t)(row0 + 8) * PP + p) =
                    make_float2(acc[mt][nt][2], acc[mt][nt][3]);
            }
        }
    }
}

// ---------------- 3) fused quantile threshold + CSR segment max ----------------
// One block per column b; 2 blocks/SM. 4096-bin histogram (lower atomic
// contention, ~23 bin-t candidates); NO clamps: |x| <= 1+1e-4 by Cauchy-Schwarz
// so the affine map with lo=-1.02 can never produce an out-of-range bin.
// Identical classification expression in both passes keeps selection exact;
// output is bit-identical to the clamped 1024-bin version.
#define QBINS 4096
#define QCAP  1024
#define QSMEM ((PP + QCAP + QBINS) * 4)

__global__ __launch_bounds__(1024, 2) void quantile_segmax_kernel() {
    extern __shared__ float sm[];
    float* col = sm;                       // PP
    float* cand = sm + PP;                 // QCAP
    int* hist = (int*)(cand + QCAP);       // QBINS
    __shared__ int s_t, s_cnt, s_rankAbove;
    __shared__ unsigned int s_minAbove;
    __shared__ int gsum[64];
    __shared__ float s_thr, s_v1000, s_v1001;

    int b = blockIdx.x, tid = threadIdx.x, nt = blockDim.x;
    for (int i = tid; i < QBINS; i += nt) hist[i] = 0;
    if (tid == 0) { s_cnt = 0; s_minAbove = 0xFFFFFFFFu; }
    __syncthreads();

    const float lo = -1.02f;
    const float scale = (float)QBINS / 2.04f;

    // fused: load column into smem + histogram (no clamps)
    {
        const float4* src4 = reinterpret_cast<const float4*>(g_xT + (size_t)b * PP);
        float4* col4 = reinterpret_cast<float4*>(col);
        for (int i = tid; i < PP / 4; i += nt) {
            float4 v = src4[i];
            col4[i] = v;
            atomicAdd(&hist[(int)((v.x - lo) * scale)], 1);
            atomicAdd(&hist[(int)((v.y - lo) * scale)], 1);
            atomicAdd(&hist[(int)((v.z - lo) * scale)], 1);
            atomicAdd(&hist[(int)((v.w - lo) * scale)], 1);
        }
    }
    __syncthreads();

    // two-level suffix search: largest bin t with count(bin >= t) >= 1001
    if (tid < 64) {
        int s = 0;
#pragma unroll 8
        for (int j = 0; j < 64; j++) s += hist[tid * 64 + j];
        gsum[tid] = s;
    }
    __syncthreads();
    if (tid == 0) {
        int run = 0, gi = 63;
        for (; gi >= 0; --gi) { run += gsum[gi]; if (run >= 1001) break; }
        int above = run - gsum[gi];
        int suf = above, j = 63;
        for (; j >= 0; --j) { suf += hist[gi * 64 + j]; if (suf >= 1001) break; }
        s_t = gi * 64 + j;
        s_rankAbove = suf - hist[gi * 64 + j];   // count with bin > t (<= 1000)
    }
    __syncthreads();
    int t = s_t;

    // gather bin==t candidates; min of values with bin>t (same classification)
    for (int i = tid; i < PP; i += nt) {
        float v = col[i];
        int bin = (int)((v - lo) * scale);
        if (bin == t) {
            int idx = atomicAdd(&s_cnt, 1);
            if (idx < QCAP) cand[idx] = v;
        } else if (bin > t) {
            atomicMin(&s_minAbove, f2key(v));
        }
    }
    __syncthreads();

    // rank-by-counting among m candidates (descending ranks r0=999-R1, r1=1000-R1)
    {
        int m = min(s_cnt, QCAP);
        int R1 = s_rankAbove;
        int r0 = 999 - R1, r1 = 1000 - R1;
        for (int i = tid; i < m; i += nt) {
            float vi = cand[i];
            int cnt = 0;
            for (int j = 0; j < m; ++j) {
                float vj = cand[j];
                cnt += (vj > vi) || (vj == vi && j < i);
            }
            if (cnt == r0) s_v1000 = vi;
            if (cnt == r1) s_v1001 = vi;
        }
    }
    __syncthreads();

    if (tid == 0) {
        int R1 = s_rankAbove;
        float v1000 = (R1 >= 1000) ? key2f(s_minAbove) : s_v1000;
        float v1001 = s_v1001;
        // replicate jnp.quantile 'linear' in f32
        float qq = __fmul_rn(0.95f, (float)(PP - 1));
        float fl = floorf(qq);
        float w_hi = __fadd_rn(qq, -fl);
        float w_lo = __fadd_rn(fl + 1.0f, -qq);
        s_thr = __fadd_rn(__fmul_rn(v1001, w_lo), __fmul_rn(v1000, w_hi));
    }
    __syncthreads();
    float thr = s_thr;

    // CSR segment max: one thread per class; CONTIGUOUS writes to outT[b][c].
    float* dstrow = g_outT + (size_t)b * CC;
    for (int c = tid; c < CC; c += nt) {
        int s0 = g_cstart[c], s1 = g_cstart[c + 1];
        float mx = -__int_as_float(0x7f800000);  // -inf (classes non-empty)
        for (int i = s0; i < s1; ++i) {
            float v = col[i];
            v = (v < thr) ? 0.0f : v;
            mx = fmaxf(mx, v);
        }
        dstrow[c] = mx;
    }
}

// ---------------- 4) tile transpose outT[b][c] -> out[c][b] ----------------
__global__ __launch_bounds__(256) void transpose_kernel(float* __restrict__ out) {
    __shared__ float tile[32][33];
    int c0 = blockIdx.x * 32, b0 = blockIdx.y * 32;
    int tx = threadIdx.x & 31, ty = threadIdx.x >> 5;  // 32 x 8
#pragma unroll
    for (int k = 0; k < 4; ++k) {
        int bb = b0 + ty + k * 8, c = c0 + tx;
        if (c < CC) tile[ty + k * 8][tx] = g_outT[(size_t)bb * CC + c];
    }
    __syncthreads();
#pragma unroll
    for (int k = 0; k < 4; ++k) {
        int c = c0 + ty + k * 8;
        if (c < CC) out[(size_t)c * BB + b0 + tx] = tile[tx][ty + k * 8];
    }
}

// ---------------- launch ----------------
extern "C" void kernel_launch(void* const* d_in, const int* in_sizes, int n_in,
                              void* d_out, int out_size) {
    const float* data = nullptr;
    const float* w1 = nullptr;
    const void* segs = nullptr;
    for (int i = 0; i < n_in; ++i) {
        long long sz = in_sizes[i];
        if (sz == (long long)BB * DD) data = (const float*)d_in[i];
        else if (sz == (long long)PP * DD) w1 = (const float*)d_in[i];
        else if (sz == (long long)PP) segs = d_in[i];
    }
    if (!data) data = (const float*)d_in[0];
    if (!w1) w1 = (const float*)d_in[1];
    if (!segs) segs = d_in[2];
    float* out = (float*)d_out;

    norm_split_kernel<<<BB + PPAD, 128>>>(data, w1);
    seg_csr_kernel<<<(PP + 255) / 256, 256>>>(segs);

    cudaFuncSetAttribute(tc_gemm_kernel,
                         cudaFuncAttributeMaxDynamicSharedMemorySize, GSMEM);
    tc_gemm_kernel<<<dim3(MTILES, NTILES), 256, GSMEM>>>();

    cudaFuncSetAttribute(quantile_segmax_kernel,
                         cudaFuncAttributeMaxDynamicSharedMemorySize, QSMEM);
    quantile_segmax_kernel<<<BB, 1024, QSMEM>>>();

    transpose_kernel<<<dim3((CC + 31) / 32, BB / 32), 256>>>(out);
}

// round 15
// speedup vs baseline: 1.0210x; 1.0210x over previous
#include <cuda_runtime.h>
#include <cuda_bf16.h>
#include <cuda_fp16.h>
#include <cstdint>
#include <cstddef>

// ---------------- Problem constants ----------------
#define PP 20000   // total proxies
#define CC 1000    // num classes
#define DD 512     // embedding dim
#define BB 4096    // eval batch
#define PPAD 20224 // 158*128 padded proxies
#define NTILES 158 // p tiles of 128
#define MTILES 32  // b tiles of 128
#define NSTAGES 24 // virtual K = [h*m(512) | m*h(512) | h*h(512)], 64 fp16 per stage
#define SCALE_STAGE 15  // after this stage: acc *= 2^-11 (cross terms done)
#define STAGEB 32768    // per-buffer smem: A 16KB + B 16KB
#define NBUF 3
#define GSMEM (NBUF * STAGEB)   // 96KB -> 2 CTAs per SM

// ---------------- Device scratch (no allocs allowed) ----------------
__device__ float  g_xT[(size_t)BB * PP];         // 327 MB  x transposed [b][p]
__device__ float  g_outT[(size_t)BB * CC];       // 16 MB   out transposed [b][c]
__device__ int    g_cstart[CC + 1];              // CSR class offsets (ids sorted)
__device__ __half g_Ah[2 * (size_t)BB * DD];     // data fp16 terms: h, m*2^11
__device__ __half g_Bh[2 * (size_t)PPAD * DD];   // w1 fp16 terms: h, m*2^11 (pad 0)

#define ASZH ((size_t)BB * DD * 2)               // bytes per A term
#define BSZH ((size_t)PPAD * DD * 2)             // bytes per B term

// ---------------- small helpers ----------------
__device__ __forceinline__ uint32_t smem_u32(const void* p) {
    uint32_t a;
    asm("{ .reg .u64 t; cvta.to.shared.u64 t, %1; cvt.u32.u64 %0, t; }"
        : "=r"(a) : "l"(p));
    return a;
}
#define CP_ASYNC16(dst, src) \
    asm volatile("cp.async.cg.shared.global [%0], [%1], 16;" :: "r"(dst), "l"(src))
#define CP_COMMIT asm volatile("cp.async.commit_group;" ::: "memory")
#define CP_WAIT1  asm volatile("cp.async.wait_group 1;" ::: "memory")
#define CP_WAIT0  asm volatile("cp.async.wait_group 0;" ::: "memory")

#define MMA_F16(c, a0, a1, a2, a3, b0, b1) \
    asm volatile( \
        "mma.sync.aligned.m16n8k16.row.col.f32.f16.f16.f32 " \
        "{%0,%1,%2,%3}, {%4,%5,%6,%7}, {%8,%9}, {%0,%1,%2,%3};" \
        : "+f"((c)[0]), "+f"((c)[1]), "+f"((c)[2]), "+f"((c)[3]) \
        : "r"(a0), "r"(a1), "r"(a2), "r"(a3), "r"(b0), "r"(b1))

#define LDSM_X4(r0, r1, r2, r3, addr) \
    asm volatile("ldmatrix.sync.aligned.m8n8.x4.shared.b16 {%0,%1,%2,%3}, [%4];" \
        : "=r"(r0), "=r"(r1), "=r"(r2), "=r"(r3) : "r"(addr))

// Order-preserving float<->uint key (for atomic min on floats)
__device__ __forceinline__ unsigned int f2key(float f) {
    unsigned int u = __float_as_uint(f);
    return (u & 0x80000000u) ? ~u : (u | 0x80000000u);
}
__device__ __forceinline__ float key2f(unsigned int k) {
    unsigned int u = (k & 0x80000000u) ? (k & 0x7FFFFFFFu) : ~k;
    return __uint_as_float(u);
}

// ---------------- 1) L2-normalize + scaled 2-term fp16 split (fused A+B) -----
// h = fp16(x); m~ = fp16((x - h) * 2^11). blocks [0,BB) -> data, rest -> w1.
__global__ void norm_split_kernel(const float* __restrict__ data,
                                  const float* __restrict__ w1) {
    int blk = blockIdx.x;
    int tid = threadIdx.x;  // 128
    const float* in;
    __half *hp, *mp;
    bool valid;
    if (blk < BB) {
        in = data + ((size_t)blk << 9);
        hp = g_Ah + ((size_t)blk << 9);
        mp = hp + (size_t)BB * DD;
        valid = true;
    } else {
        int row = blk - BB;
        in = w1 + ((size_t)row << 9);
        hp = g_Bh + ((size_t)row << 9);
        mp = hp + (size_t)PPAD * DD;
        valid = (row < PP);
    }
    if (!valid) {  // zero-pad rows -> MMA contributes 0
        uint2 z = make_uint2(0u, 0u);
        reinterpret_cast<uint2*>(hp)[tid] = z;
        reinterpret_cast<uint2*>(mp)[tid] = z;
        return;
    }
    float4 v = reinterpret_cast<const float4*>(in)[tid];
    float ss = v.x * v.x + v.y * v.y + v.z * v.z + v.w * v.w;
#pragma unroll
    for (int o = 16; o > 0; o >>= 1) ss += __shfl_xor_sync(0xffffffffu, ss, o);
    __shared__ float ws[4];
    if ((tid & 31) == 0) ws[tid >> 5] = ss;
    __syncthreads();
    float nrm = fmaxf(sqrtf(ws[0] + ws[1] + ws[2] + ws[3]), 1e-12f);
    float x[4] = {v.x / nrm, v.y / nrm, v.z / nrm, v.w / nrm};
    __half hh[4], mm[4];
#pragma unroll
    for (int j = 0; j < 4; ++j) {
        __half h = __float2half_rn(x[j]);
        float r = x[j] - __half2float(h);
        hh[j] = h;
        mm[j] = __float2half_rn(r * 2048.0f);
    }
    __half2* h2 = reinterpret_cast<__half2*>(hp);
    __half2* m2 = reinterpret_cast<__half2*>(mp);
    __half2 t;
    t.x = hh[0]; t.y = hh[1]; h2[2 * tid] = t;
    t.x = hh[2]; t.y = hh[3]; h2[2 * tid + 1] = t;
    t.x = mm[0]; t.y = mm[1]; m2[2 * tid] = t;
    t.x = mm[2]; t.y = mm[3]; m2[2 * tid + 1] = t;
}

// ---------------- fused segment-id decode + CSR offsets ----------------
__global__ void seg_csr_kernel(const void* __restrict__ s) {
    const int* w = (const int*)s;
    bool is64 = (w[19999] == 0);
    int i = blockIdx.x * 256 + threadIdx.x;
    if (i < PP) {
        int v = is64 ? (int)((const long long*)s)[i] : w[i];
        v = min(max(v, 0), CC - 1);
        int prev = -1;
        if (i > 0) {
            int pv = is64 ? (int)((const long long*)s)[i - 1] : w[i - 1];
            prev = min(max(pv, 0), CC - 1);
        }
        for (int c = prev + 1; c <= v; ++c) g_cstart[c] = i;
        if (i == PP - 1)
            for (int c = v + 1; c <= CC; ++c) g_cstart[c] = PP;
    }
}

// ---------------- 2) scaled-fp16 split GEMM, 2 CTAs/SM (unchanged R12) -------
__global__ void __launch_bounds__(256, 2) tc_gemm_kernel() {
    extern __shared__ char smem[];
    const int tid = threadIdx.x;
    const int wid = tid >> 5, lane = tid & 31;
    const int wm = wid & 1, wn = wid >> 1;
    const int g = lane >> 2, tig = lane & 3;
    const int t7 = lane & 7, t15 = lane & 15;
    const int m0 = blockIdx.x * 128;
    const int n0 = blockIdx.y * 128;
    const uint32_t sbase = smem_u32(smem);

    const uint32_t a_row_off = (uint32_t)((wm * 64 + t15) << 7);
    const int a_kq_add = lane >> 4;
    const uint32_t b_row_off = (uint32_t)((wn * 32 + t7 + ((lane & 16) >> 1)) << 7);
    const int b_kq_add = (lane >> 3) & 1;

    float acc[4][4][4];
#pragma unroll
    for (int a = 0; a < 4; ++a)
#pragma unroll
        for (int b = 0; b < 4; ++b)
#pragma unroll
            for (int c = 0; c < 4; ++c) acc[a][b][c] = 0.f;

    auto load_stage = [&](int ks, int buf) {
        int grp = ks >> 3;                               // 0: h*m, 1: m*h, 2: h*h
        const char* abase = (const char*)g_Ah + ((grp == 1) ? ASZH : 0);
        const char* bbase = (const char*)g_Bh + ((grp == 0) ? BSZH : 0);
        int kbyte = (ks & 7) << 7;                       // 128B per 64 fp16
        uint32_t sbuf = sbase + buf * STAGEB;
#pragma unroll
        for (int i = 0; i < 8; ++i) {
            int idx = tid + (i << 8);
            if (idx < 1024) {                            // A: 128 rows x 8 quads
                int r = idx >> 3, q = idx & 7;
                const char* src = abase + (size_t)(m0 + r) * 1024 + kbyte + (q << 4);
                uint32_t dst = sbuf + (r << 7) + ((q ^ (r & 7)) << 4);
                CP_ASYNC16(dst, src);
            } else {                                     // B: 128 rows x 8 quads
                int j = idx - 1024;
                int r = j >> 3, q = j & 7;
                const char* src = bbase + (size_t)(n0 + r) * 1024 + kbyte + (q << 4);
                uint32_t dst = sbuf + 16384 + (r << 7) + ((q ^ (r & 7)) << 4);
                CP_ASYNC16(dst, src);
            }
        }
    };

    load_stage(0, 0); CP_COMMIT;
    load_stage(1, 1); CP_COMMIT;

#pragma unroll 1
    for (int ks = 0; ks < NSTAGES; ++ks) {
        if (ks + 1 < NSTAGES) { CP_WAIT1; } else { CP_WAIT0; }
        __syncthreads();     // stage ks resident; buffer (ks+2)%NBUF free
        if (ks + 2 < NSTAGES) { load_stage(ks + 2, (ks + 2) % NBUF); CP_COMMIT; }

        uint32_t sA = sbase + (ks % NBUF) * STAGEB;
        uint32_t sB = sA + 16384;
#pragma unroll
        for (int s = 0; s < 4; ++s) {                    // 4 x k16 per stage
            uint32_t a[4][4];
            {
                uint32_t qa = (uint32_t)(((2 * s + a_kq_add) ^ t7) << 4);
#pragma unroll
                for (int mt = 0; mt < 4; ++mt) {
                    uint32_t addr = sA + a_row_off + (uint32_t)(mt << 11) + qa;
                    LDSM_X4(a[mt][0], a[mt][1], a[mt][2], a[mt][3], addr);
                }
            }
            uint32_t bf[2][4];
            {
                uint32_t qb = (uint32_t)(((2 * s + b_kq_add) ^ t7) << 4);
#pragma unroll
                for (int ntp = 0; ntp < 2; ++ntp) {
                    uint32_t addr = sB + b_row_off + (uint32_t)(ntp << 11) + qb;
                    LDSM_X4(bf[ntp][0], bf[ntp][1], bf[ntp][2], bf[ntp][3], addr);
                }
            }
#pragma unroll
            for (int nt = 0; nt < 4; ++nt) {
                uint32_t b0 = bf[nt >> 1][(nt & 1) * 2];
                uint32_t b1 = bf[nt >> 1][(nt & 1) * 2 + 1];
#pragma unroll
                for (int mt = 0; mt < 4; ++mt)
                    MMA_F16(acc[mt][nt], a[mt][0], a[mt][1], a[mt][2], a[mt][3], b0, b1);
            }
        }

        if (ks == SCALE_STAGE) {  // cross terms accumulated: undo the 2^11 scale
#pragma unroll
            for (int mt = 0; mt < 4; ++mt)
#pragma unroll
                for (int nt = 0; nt < 4; ++nt)
#pragma unroll
                    for (int c = 0; c < 4; ++c)
                        acc[mt][nt][c] *= 4.8828125e-4f;   // exact 2^-11
        }
    }

    // epilogue: direct fp32 stores (32B-coalesced per quad)
#pragma unroll
    for (int mt = 0; mt < 4; ++mt) {
        int row0 = m0 + wm * 64 + mt * 16 + g;
#pragma unroll
        for (int nt = 0; nt < 4; ++nt) {
            int p = n0 + wn * 32 + nt * 8 + tig * 2;
            if (p < PP) {
                *reinterpret_cast<float2*>(g_xT + (size_t)row0 * PP + p) =
                    make_float2(acc[mt][nt][0], acc[mt][nt][1]);
                *reinterpret_cast<float2*>(g_xT + (size_t)(row0 + 8) * PP + p) =
                    make_float2(acc[mt][nt][2], acc[mt][nt][3]);
            }
        }
    }
}

// ---------------- 3) fused quantile threshold + CSR segment max ----------------
// One block per column b; 2 blocks/SM. R13 classification (1024 bins, clamps —
// proven). Column staged via cp.async (deep pipeline -> DRAM bandwidth-bound
// instead of latency-bound); histogram runs out of smem afterwards.
#define QBINS 1024
#define QCAP  1024
#define QSMEM ((PP + QCAP + QBINS) * 4)

__global__ __launch_bounds__(1024, 2) void quantile_segmax_kernel() {
    extern __shared__ float sm[];
    float* col = sm;                       // PP
    float* cand = sm + PP;                 // QCAP
    int* hist = (int*)(cand + QCAP);       // QBINS
    __shared__ int s_t, s_cnt, s_rankAbove;
    __shared__ unsigned int s_minAbove;
    __shared__ int gsum[32];
    __shared__ float s_thr, s_v1000, s_v1001;

    int b = blockIdx.x, tid = threadIdx.x, nt = blockDim.x;
    uint32_t colbase = smem_u32(col);

    // stage column into smem via cp.async: no register dependencies, deep
    // in-flight queue -> the 80KB column read streams at DRAM bandwidth.
    {
        const char* src = (const char*)(g_xT + (size_t)b * PP);
        for (int i = tid; i < PP / 4; i += nt)
            CP_ASYNC16(colbase + (uint32_t)(i << 4), src + ((size_t)i << 4));
        CP_COMMIT;
    }
    for (int i = tid; i < QBINS; i += nt) hist[i] = 0;
    if (tid == 0) { s_cnt = 0; s_minAbove = 0xFFFFFFFFu; }
    CP_WAIT0;
    __syncthreads();

    const float lo = -1.001f;
    const float scale = (float)QBINS / 2.002f;

    // histogram from smem
    for (int i = tid; i < PP; i += nt) {
        int bin = (int)((col[i] - lo) * scale);
        bin = min(max(bin, 0), QBINS - 1);
        atomicAdd(&hist[bin], 1);
    }
    __syncthreads();

    // two-level suffix search: largest bin t with count(bin >= t) >= 1001
    if (tid < 32) {
        int s = 0;
#pragma unroll 8
        for (int j = 0; j < 32; j++) s += hist[tid * 32 + j];
        gsum[tid] = s;
    }
    __syncthreads();
    if (tid == 0) {
        int run = 0, gi = 31;
        for (; gi >= 0; --gi) { run += gsum[gi]; if (run >= 1001) break; }
        int above = run - gsum[gi];
        int suf = above, j = 31;
        for (; j >= 0; --j) { suf += hist[gi * 32 + j]; if (suf >= 1001) break; }
        s_t = gi * 32 + j;
        s_rankAbove = suf - hist[gi * 32 + j];   // count with bin > t (<= 1000)
    }
    __syncthreads();
    int t = s_t;

    // gather bin==t candidates; min of values with bin>t
    for (int i = tid; i < PP; i += nt) {
        float v = col[i];
        int bin = (int)((v - lo) * scale);
        bin = min(max(bin, 0), QBINS - 1);
        if (bin == t) {
            int idx = atomicAdd(&s_cnt, 1);
            if (idx < QCAP) cand[idx] = v;
        } else if (bin > t) {
            atomicMin(&s_minAbove, f2key(v));
        }
    }
    __syncthreads();

    // rank-by-counting among m candidates (descending ranks r0=999-R1, r1=1000-R1)
    {
        int m = min(s_cnt, QCAP);
        int R1 = s_rankAbove;
        int r0 = 999 - R1, r1 = 1000 - R1;
        for (int i = tid; i < m; i += nt) {
            float vi = cand[i];
            int cnt = 0;
            for (int j = 0; j < m; ++j) {
                float vj = cand[j];
                cnt += (vj > vi) || (vj == vi && j < i);
            }
            if (cnt == r0) s_v1000 = vi;
            if (cnt == r1) s_v1001 = vi;
        }
    }
    __syncthreads();

    if (tid == 0) {
        int R1 = s_rankAbove;
        float v1000 = (R1 >= 1000) ? key2f(s_minAbove) : s_v1000;
        float v1001 = s_v1001;
        // replicate jnp.quantile 'linear' in f32
        float qq = __fmul_rn(0.95f, (float)(PP - 1));
        float fl = floorf(qq);
        float w_hi = __fadd_rn(qq, -fl);
        float w_lo = __fadd_rn(fl + 1.0f, -qq);
        s_thr = __fadd_rn(__fmul_rn(v1001, w_lo), __fmul_rn(v1000, w_hi));
    }
    __syncthreads();
    float thr = s_thr;

    // CSR segment max: one thread per class; CONTIGUOUS writes to outT[b][c].
    float* dstrow = g_outT + (size_t)b * CC;
    for (int c = tid; c < CC; c += nt) {
        int s0 = g_cstart[c], s1 = g_cstart[c + 1];
        float mx = -__int_as_float(0x7f800000);  // -inf (classes non-empty)
        for (int i = s0; i < s1; ++i) {
            float v = col[i];
            v = (v < thr) ? 0.0f : v;
            mx = fmaxf(mx, v);
        }
        dstrow[c] = mx;
    }
}

// ---------------- 4) tile transpose outT[b][c] -> out[c][b] ----------------
__global__ __launch_bounds__(256) void transpose_kernel(float* __restrict__ out) {
    __shared__ float tile[32][33];
    int c0 = blockIdx.x * 32, b0 = blockIdx.y * 32;
    int tx = threadIdx.x & 31, ty = threadIdx.x >> 5;  // 32 x 8
#pragma unroll
    for (int k = 0; k < 4; ++k) {
        int bb = b0 + ty + k * 8, c = c0 + tx;
        if (c < CC) tile[ty + k * 8][tx] = g_outT[(size_t)bb * CC + c];
    }
    __syncthreads();
#pragma unroll
    for (int k = 0; k < 4; ++k) {
        int c = c0 + ty + k * 8;
        if (c < CC) out[(size_t)c * BB + b0 + tx] = tile[tx][ty + k * 8];
    }
}

// ---------------- launch ----------------
extern "C" void kernel_launch(void* const* d_in, const int* in_sizes, int n_in,
                              void* d_out, int out_size) {
    const float* data = nullptr;
    const float* w1 = nullptr;
    const void* segs = nullptr;
    for (int i = 0; i < n_in; ++i) {
        long long sz = in_sizes[i];
        if (sz == (long long)BB * DD) data = (const float*)d_in[i];
        else if (sz == (long long)PP * DD) w1 = (const float*)d_in[i];
        else if (sz == (long long)PP) segs = d_in[i];
    }
    if (!data) data = (const float*)d_in[0];
    if (!w1) w1 = (const float*)d_in[1];
    if (!segs) segs = d_in[2];
    float* out = (float*)d_out;

    norm_split_kernel<<<BB + PPAD, 128>>>(data, w1);
    seg_csr_kernel<<<(PP + 255) / 256, 256>>>(segs);

    cudaFuncSetAttribute(tc_gemm_kernel,
                         cudaFuncAttributeMaxDynamicSharedMemorySize, GSMEM);
    tc_gemm_kernel<<<dim3(MTILES, NTILES), 256, GSMEM>>>();

    cudaFuncSetAttribute(quantile_segmax_kernel,
                         cudaFuncAttributeMaxDynamicSharedMemorySize, QSMEM);
    quantile_segmax_kernel<<<BB, 1024, QSMEM>>>();

    transpose_kernel<<<dim3((CC + 31) / 32, BB / 32), 256>>>(out);
}

// round 16
// speedup vs baseline: 1.0333x; 1.0121x over previous
#include <cuda_runtime.h>
#include <cuda_bf16.h>
#include <cuda_fp16.h>
#include <cstdint>
#include <cstddef>

// ---------------- Problem constants ----------------
#define PP 20000   // total proxies
#define CC 1000    // num classes
#define DD 512     // embedding dim
#define BB 4096    // eval batch
#define PPAD 20224 // 158*128 padded proxies
#define NTILES 158 // p tiles of 128
#define MTILES 32  // b tiles of 128
#define NSTAGES 24 // virtual K = [h*m(512) | m*h(512) | h*h(512)], 64 fp16 per stage
#define SCALE_STAGE 15  // after this stage: acc *= 2^-11 (cross terms done)
#define STAGEB 32768    // per-buffer smem: A 16KB + B 16KB
#define NBUF 3
#define GSMEM (NBUF * STAGEB)   // 96KB -> 2 CTAs per SM

// ---------------- Device scratch (no allocs allowed) ----------------
__device__ float  g_xT[(size_t)BB * PP];         // 327 MB  x transposed [b][p]
__device__ float  g_outT[(size_t)BB * CC];       // 16 MB   out transposed [b][c]
__device__ int    g_cstart[CC + 1];              // CSR class offsets (ids sorted)
__device__ __half g_Ah[2 * (size_t)BB * DD];     // data fp16 terms: h, m*2^11
__device__ __half g_Bh[2 * (size_t)PPAD * DD];   // w1 fp16 terms: h, m*2^11 (pad 0)

#define ASZH ((size_t)BB * DD * 2)               // bytes per A term
#define BSZH ((size_t)PPAD * DD * 2)             // bytes per B term

// ---------------- small helpers ----------------
__device__ __forceinline__ uint32_t smem_u32(const void* p) {
    uint32_t a;
    asm("{ .reg .u64 t; cvta.to.shared.u64 t, %1; cvt.u32.u64 %0, t; }"
        : "=r"(a) : "l"(p));
    return a;
}
#define CP_ASYNC16(dst, src) \
    asm volatile("cp.async.cg.shared.global [%0], [%1], 16;" :: "r"(dst), "l"(src))
#define CP_COMMIT asm volatile("cp.async.commit_group;" ::: "memory")
#define CP_WAIT1  asm volatile("cp.async.wait_group 1;" ::: "memory")
#define CP_WAIT0  asm volatile("cp.async.wait_group 0;" ::: "memory")

#define MMA_F16(c, a0, a1, a2, a3, b0, b1) \
    asm volatile( \
        "mma.sync.aligned.m16n8k16.row.col.f32.f16.f16.f32 " \
        "{%0,%1,%2,%3}, {%4,%5,%6,%7}, {%8,%9}, {%0,%1,%2,%3};" \
        : "+f"((c)[0]), "+f"((c)[1]), "+f"((c)[2]), "+f"((c)[3]) \
        : "r"(a0), "r"(a1), "r"(a2), "r"(a3), "r"(b0), "r"(b1))

#define LDSM_X4(r0, r1, r2, r3, addr) \
    asm volatile("ldmatrix.sync.aligned.m8n8.x4.shared.b16 {%0,%1,%2,%3}, [%4];" \
        : "=r"(r0), "=r"(r1), "=r"(r2), "=r"(r3) : "r"(addr))

// Order-preserving float<->uint key (for atomic min on floats)
__device__ __forceinline__ unsigned int f2key(float f) {
    unsigned int u = __float_as_uint(f);
    return (u & 0x80000000u) ? ~u : (u | 0x80000000u);
}
__device__ __forceinline__ float key2f(unsigned int k) {
    unsigned int u = (k & 0x80000000u) ? (k & 0x7FFFFFFFu) : ~k;
    return __uint_as_float(u);
}

// ---------------- 1) L2-normalize + scaled 2-term fp16 split (fused A+B) -----
// h = fp16(x); m~ = fp16((x - h) * 2^11). blocks [0,BB) -> data, rest -> w1.
__global__ void norm_split_kernel(const float* __restrict__ data,
                                  const float* __restrict__ w1) {
    int blk = blockIdx.x;
    int tid = threadIdx.x;  // 128
    const float* in;
    __half *hp, *mp;
    bool valid;
    if (blk < BB) {
        in = data + ((size_t)blk << 9);
        hp = g_Ah + ((size_t)blk << 9);
        mp = hp + (size_t)BB * DD;
        valid = true;
    } else {
        int row = blk - BB;
        in = w1 + ((size_t)row << 9);
        hp = g_Bh + ((size_t)row << 9);
        mp = hp + (size_t)PPAD * DD;
        valid = (row < PP);
    }
    if (!valid) {  // zero-pad rows -> MMA contributes 0
        uint2 z = make_uint2(0u, 0u);
        reinterpret_cast<uint2*>(hp)[tid] = z;
        reinterpret_cast<uint2*>(mp)[tid] = z;
        return;
    }
    float4 v = reinterpret_cast<const float4*>(in)[tid];
    float ss = v.x * v.x + v.y * v.y + v.z * v.z + v.w * v.w;
#pragma unroll
    for (int o = 16; o > 0; o >>= 1) ss += __shfl_xor_sync(0xffffffffu, ss, o);
    __shared__ float ws[4];
    if ((tid & 31) == 0) ws[tid >> 5] = ss;
    __syncthreads();
    float nrm = fmaxf(sqrtf(ws[0] + ws[1] + ws[2] + ws[3]), 1e-12f);
    float x[4] = {v.x / nrm, v.y / nrm, v.z / nrm, v.w / nrm};
    __half hh[4], mm[4];
#pragma unroll
    for (int j = 0; j < 4; ++j) {
        __half h = __float2half_rn(x[j]);
        float r = x[j] - __half2float(h);
        hh[j] = h;
        mm[j] = __float2half_rn(r * 2048.0f);
    }
    __half2* h2 = reinterpret_cast<__half2*>(hp);
    __half2* m2 = reinterpret_cast<__half2*>(mp);
    __half2 t;
    t.x = hh[0]; t.y = hh[1]; h2[2 * tid] = t;
    t.x = hh[2]; t.y = hh[3]; h2[2 * tid + 1] = t;
    t.x = mm[0]; t.y = mm[1]; m2[2 * tid] = t;
    t.x = mm[2]; t.y = mm[3]; m2[2 * tid + 1] = t;
}

// ---------------- fused segment-id decode + CSR offsets ----------------
__global__ void seg_csr_kernel(const void* __restrict__ s) {
    const int* w = (const int*)s;
    bool is64 = (w[19999] == 0);
    int i = blockIdx.x * 256 + threadIdx.x;
    if (i < PP) {
        int v = is64 ? (int)((const long long*)s)[i] : w[i];
        v = min(max(v, 0), CC - 1);
        int prev = -1;
        if (i > 0) {
            int pv = is64 ? (int)((const long long*)s)[i - 1] : w[i - 1];
            prev = min(max(pv, 0), CC - 1);
        }
        for (int c = prev + 1; c <= v; ++c) g_cstart[c] = i;
        if (i == PP - 1)
            for (int c = v + 1; c <= CC; ++c) g_cstart[c] = PP;
    }
}

// ---------------- 2) scaled-fp16 split GEMM, 2 CTAs/SM (unchanged R12) -------
__global__ void __launch_bounds__(256, 2) tc_gemm_kernel() {
    extern __shared__ char smem[];
    const int tid = threadIdx.x;
    const int wid = tid >> 5, lane = tid & 31;
    const int wm = wid & 1, wn = wid >> 1;
    const int g = lane >> 2, tig = lane & 3;
    const int t7 = lane & 7, t15 = lane & 15;
    const int m0 = blockIdx.x * 128;
    const int n0 = blockIdx.y * 128;
    const uint32_t sbase = smem_u32(smem);

    const uint32_t a_row_off = (uint32_t)((wm * 64 + t15) << 7);
    const int a_kq_add = lane >> 4;
    const uint32_t b_row_off = (uint32_t)((wn * 32 + t7 + ((lane & 16) >> 1)) << 7);
    const int b_kq_add = (lane >> 3) & 1;

    float acc[4][4][4];
#pragma unroll
    for (int a = 0; a < 4; ++a)
#pragma unroll
        for (int b = 0; b < 4; ++b)
#pragma unroll
            for (int c = 0; c < 4; ++c) acc[a][b][c] = 0.f;

    auto load_stage = [&](int ks, int buf) {
        int grp = ks >> 3;                               // 0: h*m, 1: m*h, 2: h*h
        const char* abase = (const char*)g_Ah + ((grp == 1) ? ASZH : 0);
        const char* bbase = (const char*)g_Bh + ((grp == 0) ? BSZH : 0);
        int kbyte = (ks & 7) << 7;                       // 128B per 64 fp16
        uint32_t sbuf = sbase + buf * STAGEB;
#pragma unroll
        for (int i = 0; i < 8; ++i) {
            int idx = tid + (i << 8);
            if (idx < 1024) {                            // A: 128 rows x 8 quads
                int r = idx >> 3, q = idx & 7;
                const char* src = abase + (size_t)(m0 + r) * 1024 + kbyte + (q << 4);
                uint32_t dst = sbuf + (r << 7) + ((q ^ (r & 7)) << 4);
                CP_ASYNC16(dst, src);
            } else {                                     // B: 128 rows x 8 quads
                int j = idx - 1024;
                int r = j >> 3, q = j & 7;
                const char* src = bbase + (size_t)(n0 + r) * 1024 + kbyte + (q << 4);
                uint32_t dst = sbuf + 16384 + (r << 7) + ((q ^ (r & 7)) << 4);
                CP_ASYNC16(dst, src);
            }
        }
    };

    load_stage(0, 0); CP_COMMIT;
    load_stage(1, 1); CP_COMMIT;

#pragma unroll 1
    for (int ks = 0; ks < NSTAGES; ++ks) {
        if (ks + 1 < NSTAGES) { CP_WAIT1; } else { CP_WAIT0; }
        __syncthreads();     // stage ks resident; buffer (ks+2)%NBUF free
        if (ks + 2 < NSTAGES) { load_stage(ks + 2, (ks + 2) % NBUF); CP_COMMIT; }

        uint32_t sA = sbase + (ks % NBUF) * STAGEB;
        uint32_t sB = sA + 16384;
#pragma unroll
        for (int s = 0; s < 4; ++s) {                    // 4 x k16 per stage
            uint32_t a[4][4];
            {
                uint32_t qa = (uint32_t)(((2 * s + a_kq_add) ^ t7) << 4);
#pragma unroll
                for (int mt = 0; mt < 4; ++mt) {
                    uint32_t addr = sA + a_row_off + (uint32_t)(mt << 11) + qa;
                    LDSM_X4(a[mt][0], a[mt][1], a[mt][2], a[mt][3], addr);
                }
            }
            uint32_t bf[2][4];
            {
                uint32_t qb = (uint32_t)(((2 * s + b_kq_add) ^ t7) << 4);
#pragma unroll
                for (int ntp = 0; ntp < 2; ++ntp) {
                    uint32_t addr = sB + b_row_off + (uint32_t)(ntp << 11) + qb;
                    LDSM_X4(bf[ntp][0], bf[ntp][1], bf[ntp][2], bf[ntp][3], addr);
                }
            }
#pragma unroll
            for (int nt = 0; nt < 4; ++nt) {
                uint32_t b0 = bf[nt >> 1][(nt & 1) * 2];
                uint32_t b1 = bf[nt >> 1][(nt & 1) * 2 + 1];
#pragma unroll
                for (int mt = 0; mt < 4; ++mt)
                    MMA_F16(acc[mt][nt], a[mt][0], a[mt][1], a[mt][2], a[mt][3], b0, b1);
            }
        }

        if (ks == SCALE_STAGE) {  // cross terms accumulated: undo the 2^11 scale
#pragma unroll
            for (int mt = 0; mt < 4; ++mt)
#pragma unroll
                for (int nt = 0; nt < 4; ++nt)
#pragma unroll
                    for (int c = 0; c < 4; ++c)
                        acc[mt][nt][c] *= 4.8828125e-4f;   // exact 2^-11
        }
    }

    // epilogue: direct fp32 stores (32B-coalesced per quad)
#pragma unroll
    for (int mt = 0; mt < 4; ++mt) {
        int row0 = m0 + wm * 64 + mt * 16 + g;
#pragma unroll
        for (int nt = 0; nt < 4; ++nt) {
            int p = n0 + wn * 32 + nt * 8 + tig * 2;
            if (p < PP) {
                *reinterpret_cast<float2*>(g_xT + (size_t)row0 * PP + p) =
                    make_float2(acc[mt][nt][0], acc[mt][nt][1]);
                *reinterpret_cast<float2*>(g_xT + (size_t)(row0 + 8) * PP + p) =
                    make_float2(acc[mt][nt][2], acc[mt][nt][3]);
            }
        }
    }
}

// ---------------- 3) fused quantile threshold + CSR segment max ----------------
// One block per column b; 2 blocks/SM. Issue-bound -> instruction diet:
// float4 smem loads in both 20000-element passes, clamp-free bin map
// bin = (int)(v*500 + 512)  (lo=-1.024, scale=500; |x| <= 1+1e-3 by
// Cauchy-Schwarz leaves 2.3% margin to [0,1024) -> clamps are dead code).
// Selection extracts exact order statistics for any valid bin partition, so
// the output is bit-identical to the clamped variant.
#define QBINS 1024
#define QCAP  1024
#define QSMEM ((PP + QCAP + QBINS) * 4)

__global__ __launch_bounds__(1024, 2) void quantile_segmax_kernel() {
    extern __shared__ float sm[];
    float* col = sm;                       // PP
    float* cand = sm + PP;                 // QCAP
    int* hist = (int*)(cand + QCAP);       // QBINS
    __shared__ int s_t, s_cnt, s_rankAbove;
    __shared__ unsigned int s_minAbove;
    __shared__ int gsum[32];
    __shared__ float s_thr, s_v1000, s_v1001;

    int b = blockIdx.x, tid = threadIdx.x, nt = blockDim.x;
    uint32_t colbase = smem_u32(col);

    // stage column into smem via cp.async (deep in-flight queue)
    {
        const char* src = (const char*)(g_xT + (size_t)b * PP);
        for (int i = tid; i < PP / 4; i += nt)
            CP_ASYNC16(colbase + (uint32_t)(i << 4), src + ((size_t)i << 4));
        CP_COMMIT;
    }
    for (int i = tid; i < QBINS; i += nt) hist[i] = 0;
    if (tid == 0) { s_cnt = 0; s_minAbove = 0xFFFFFFFFu; }
    CP_WAIT0;
    __syncthreads();

    // histogram from smem: float4 loads, FFMA+F2I per element, no clamps
    {
        const float4* col4 = reinterpret_cast<const float4*>(col);
        for (int i = tid; i < PP / 4; i += nt) {
            float4 v = col4[i];
            atomicAdd(&hist[(int)__fmaf_rn(v.x, 500.0f, 512.0f)], 1);
            atomicAdd(&hist[(int)__fmaf_rn(v.y, 500.0f, 512.0f)], 1);
            atomicAdd(&hist[(int)__fmaf_rn(v.z, 500.0f, 512.0f)], 1);
            atomicAdd(&hist[(int)__fmaf_rn(v.w, 500.0f, 512.0f)], 1);
        }
    }
    __syncthreads();

    // two-level suffix search: largest bin t with count(bin >= t) >= 1001
    if (tid < 32) {
        int s = 0;
#pragma unroll 8
        for (int j = 0; j < 32; j++) s += hist[tid * 32 + j];
        gsum[tid] = s;
    }
    __syncthreads();
    if (tid == 0) {
        int run = 0, gi = 31;
        for (; gi >= 0; --gi) { run += gsum[gi]; if (run >= 1001) break; }
        int above = run - gsum[gi];
        int suf = above, j = 31;
        for (; j >= 0; --j) { suf += hist[gi * 32 + j]; if (suf >= 1001) break; }
        s_t = gi * 32 + j;
        s_rankAbove = suf - hist[gi * 32 + j];   // count with bin > t (<= 1000)
    }
    __syncthreads();
    int t = s_t;

    // gather bin==t candidates; min of values with bin>t (float4, no clamps)
    {
        const float4* col4 = reinterpret_cast<const float4*>(col);
        for (int i = tid; i < PP / 4; i += nt) {
            float4 v = col4[i];
            float vv[4] = {v.x, v.y, v.z, v.w};
#pragma unroll
            for (int j = 0; j < 4; ++j) {
                int bin = (int)__fmaf_rn(vv[j], 500.0f, 512.0f);
                if (bin == t) {
                    int idx = atomicAdd(&s_cnt, 1);
                    if (idx < QCAP) cand[idx] = vv[j];
                } else if (bin > t) {
                    atomicMin(&s_minAbove, f2key(vv[j]));
                }
            }
        }
    }
    __syncthreads();

    // rank-by-counting among m candidates (descending ranks r0=999-R1, r1=1000-R1)
    {
        int m = min(s_cnt, QCAP);
        int R1 = s_rankAbove;
        int r0 = 999 - R1, r1 = 1000 - R1;
        for (int i = tid; i < m; i += nt) {
            float vi = cand[i];
            int cnt = 0;
            for (int j = 0; j < m; ++j) {
                float vj = cand[j];
                cnt += (vj > vi) || (vj == vi && j < i);
            }
            if (cnt == r0) s_v1000 = vi;
            if (cnt == r1) s_v1001 = vi;
        }
    }
    __syncthreads();

    if (tid == 0) {
        int R1 = s_rankAbove;
        float v1000 = (R1 >= 1000) ? key2f(s_minAbove) : s_v1000;
        float v1001 = s_v1001;
        // replicate jnp.quantile 'linear' in f32
        float qq = __fmul_rn(0.95f, (float)(PP - 1));
        float fl = floorf(qq);
        float w_hi = __fadd_rn(qq, -fl);
        float w_lo = __fadd_rn(fl + 1.0f, -qq);
        s_thr = __fadd_rn(__fmul_rn(v1001, w_lo), __fmul_rn(v1000, w_hi));
    }
    __syncthreads();
    float thr = s_thr;

    // CSR segment max: one thread per class; CONTIGUOUS writes to outT[b][c].
    float* dstrow = g_outT + (size_t)b * CC;
    for (int c = tid; c < CC; c += nt) {
        int s0 = g_cstart[c], s1 = g_cstart[c + 1];
        float mx = -__int_as_float(0x7f800000);  // -inf (classes non-empty)
        for (int i = s0; i < s1; ++i) {
            float v = col[i];
            v = (v < thr) ? 0.0f : v;
            mx = fmaxf(mx, v);
        }
        dstrow[c] = mx;
    }
}

// ---------------- 4) tile transpose outT[b][c] -> out[c][b] ----------------
__global__ __launch_bounds__(256) void transpose_kernel(float* __restrict__ out) {
    __shared__ float tile[32][33];
    int c0 = blockIdx.x * 32, b0 = blockIdx.y * 32;
    int tx = threadIdx.x & 31, ty = threadIdx.x >> 5;  // 32 x 8
#pragma unroll
    for (int k = 0; k < 4; ++k) {
        int bb = b0 + ty + k * 8, c = c0 + tx;
        if (c < CC) tile[ty + k * 8][tx] = g_outT[(size_t)bb * CC + c];
    }
    __syncthreads();
#pragma unroll
    for (int k = 0; k < 4; ++k) {
        int c = c0 + ty + k * 8;
        if (c < CC) out[(size_t)c * BB + b0 + tx] = tile[tx][ty + k * 8];
    }
}

// ---------------- launch ----------------
extern "C" void kernel_launch(void* const* d_in, const int* in_sizes, int n_in,
                              void* d_out, int out_size) {
    const float* data = nullptr;
    const float* w1 = nullptr;
    const void* segs = nullptr;
    for (int i = 0; i < n_in; ++i) {
        long long sz = in_sizes[i];
        if (sz == (long long)BB * DD) data = (const float*)d_in[i];
        else if (sz == (long long)PP * DD) w1 = (const float*)d_in[i];
        else if (sz == (long long)PP) segs = d_in[i];
    }
    if (!data) data = (const float*)d_in[0];
    if (!w1) w1 = (const float*)d_in[1];
    if (!segs) segs = d_in[2];
    float* out = (float*)d_out;

    norm_split_kernel<<<BB + PPAD, 128>>>(data, w1);
    seg_csr_kernel<<<(PP + 255) / 256, 256>>>(segs);

    cudaFuncSetAttribute(tc_gemm_kernel,
                         cudaFuncAttributeMaxDynamicSharedMemorySize, GSMEM);
    tc_gemm_kernel<<<dim3(MTILES, NTILES), 256, GSMEM>>>();

    cudaFuncSetAttribute(quantile_segmax_kernel,
                         cudaFuncAttributeMaxDynamicSharedMemorySize, QSMEM);
    quantile_segmax_kernel<<<BB, 1024, QSMEM>>>();

    transpose_kernel<<<dim3((CC + 31) / 32, BB / 32), 256>>>(out);
}